// round 1
// baseline (speedup 1.0000x reference)
#include <cuda_runtime.h>

// LNLieBracketChannelMix on GB300
//
// out[b,g,k,n] = x[b,g,k,n] + cross(M2@d2, M1@d1)[k]
//   d1[g,k,n] = sum_f W1[g,f] * x[b,f,k,n]   (d2 with W2)
// (hat/matmul/vee Lie bracket == cross product: [hat(a),hat(b)] = hat(a x b))
//
// Fused fp32 SGEMM: per CTA, tile of 64 g x (3 k * 32 n = 96 cols), K=256 over f.
// Epilogue gathers 3 k-values per (g,n) via smem, rotates by M1/M2, cross, +x.

#define B_   8
#define F_   256
#define N_   4096

#define GT   64    // g tile
#define NT   32    // n tile
#define CT   96    // 3 * NT columns (k-major within tile)
#define FT   16    // f (reduction) chunk
#define THREADS 384

__global__ __launch_bounds__(THREADS, 2)
void lnlb_fused_kernel(const float* __restrict__ x,
                       const float* __restrict__ M1,
                       const float* __restrict__ M2,
                       const float* __restrict__ W1,
                       const float* __restrict__ W2,
                       float* __restrict__ out)
{
    extern __shared__ float smem[];
    // main-loop layout (14336 B), reused as D1/D2 (49152 B) in epilogue
    float* w1s = smem;                  // [FT][GT]  (transposed: ff-major, g contiguous)
    float* w2s = smem + FT * GT;        // [FT][GT]
    float* xs  = smem + 2 * FT * GT;    // [FT][CT]

    const int n0 = blockIdx.x * NT;
    const int g0 = blockIdx.y * GT;
    const int b  = blockIdx.z;

    const int tid = threadIdx.x;
    const int r = tid / 24;             // 0..15 -> owns g = g0 + r*4 .. +3
    const int c = tid % 24;             // 0..23 -> owns cols c*4 .. +3

    float acc1[4][4], acc2[4][4];
    #pragma unroll
    for (int i = 0; i < 4; i++)
        #pragma unroll
        for (int j = 0; j < 4; j++) { acc1[i][j] = 0.f; acc2[i][j] = 0.f; }

    const float* xb = x + (size_t)b * F_ * 3 * N_;

    for (int f0 = 0; f0 < F_; f0 += FT) {
        // Stage W tiles transposed: w[ff][g] = W[(g0+g)*F_ + f0+ff]
        #pragma unroll
        for (int i = tid; i < FT * GT; i += THREADS) {
            int g = i / FT, ff = i % FT;
            w1s[ff * GT + g] = W1[(g0 + g) * F_ + f0 + ff];
            w2s[ff * GT + g] = W2[(g0 + g) * F_ + f0 + ff];
        }
        // Stage x tile: xs[ff][k*NT+nn] = x[b, f0+ff, k, n0+nn]
        #pragma unroll
        for (int i = tid; i < FT * CT; i += THREADS) {
            int ff = i / CT, col = i % CT;
            int k = col / NT, nn = col % NT;
            xs[ff * CT + col] = xb[((size_t)(f0 + ff) * 3 + k) * N_ + n0 + nn];
        }
        __syncthreads();

        #pragma unroll
        for (int ff = 0; ff < FT; ff++) {
            float4 a1 = *(const float4*)&w1s[ff * GT + r * 4];
            float4 a2 = *(const float4*)&w2s[ff * GT + r * 4];
            float4 bb = *(const float4*)&xs[ff * CT + c * 4];
            float av1[4] = {a1.x, a1.y, a1.z, a1.w};
            float av2[4] = {a2.x, a2.y, a2.z, a2.w};
            float bv[4]  = {bb.x, bb.y, bb.z, bb.w};
            #pragma unroll
            for (int i = 0; i < 4; i++)
                #pragma unroll
                for (int j = 0; j < 4; j++) {
                    acc1[i][j] = fmaf(av1[i], bv[j], acc1[i][j]);
                    acc2[i][j] = fmaf(av2[i], bv[j], acc2[i][j]);
                }
        }
        __syncthreads();
    }

    // ---- epilogue: stage D1/D2 in smem so each thread can gather all 3 k ----
    float* D1 = smem;            // [GT][CT]
    float* D2 = smem + GT * CT;  // [GT][CT]
    #pragma unroll
    for (int i = 0; i < 4; i++)
        #pragma unroll
        for (int j = 0; j < 4; j++) {
            D1[(r * 4 + i) * CT + c * 4 + j] = acc1[i][j];
            D2[(r * 4 + i) * CT + c * 4 + j] = acc2[i][j];
        }
    __syncthreads();

    float m1[9], m2[9];
    #pragma unroll
    for (int i = 0; i < 9; i++) { m1[i] = M1[i]; m2[i] = M2[i]; }

    for (int p = tid; p < GT * NT; p += THREADS) {
        int g = p / NT, nn = p % NT;
        float e1[3], e2[3];
        #pragma unroll
        for (int k = 0; k < 3; k++) {
            e1[k] = D1[g * CT + k * NT + nn];
            e2[k] = D2[g * CT + k * NT + nn];
        }
        // rotate: dv[c] = sum_k M[c,k] * e[k]
        float dv1[3], dv2[3];
        #pragma unroll
        for (int cc = 0; cc < 3; cc++) {
            dv1[cc] = fmaf(m1[cc*3+0], e1[0], fmaf(m1[cc*3+1], e1[1], m1[cc*3+2] * e1[2]));
            dv2[cc] = fmaf(m2[cc*3+0], e2[0], fmaf(m2[cc*3+1], e2[1], m2[cc*3+2] * e2[2]));
        }
        // v = cross(dv2, dv1)
        float v0 = dv2[1] * dv1[2] - dv2[2] * dv1[1];
        float v1 = dv2[2] * dv1[0] - dv2[0] * dv1[2];
        float v2 = dv2[0] * dv1[1] - dv2[1] * dv1[0];

        size_t base = ((size_t)(b * F_ + g0 + g) * 3) * N_ + n0 + nn;
        out[base + 0 * (size_t)N_] = x[base + 0 * (size_t)N_] + v0;
        out[base + 1 * (size_t)N_] = x[base + 1 * (size_t)N_] + v1;
        out[base + 2 * (size_t)N_] = x[base + 2 * (size_t)N_] + v2;
    }
}

extern "C" void kernel_launch(void* const* d_in, const int* in_sizes, int n_in,
                              void* d_out, int out_size)
{
    const float* x  = (const float*)d_in[0];
    const float* M1 = (const float*)d_in[1];
    const float* M2 = (const float*)d_in[2];
    const float* W1 = (const float*)d_in[3];
    const float* W2 = (const float*)d_in[4];
    float* out = (float*)d_out;

    dim3 grid(N_ / NT, F_ / GT, B_);   // (128, 4, 8)
    size_t shmem = (size_t)2 * GT * CT * sizeof(float);  // 49152 B (epilogue max)
    lnlb_fused_kernel<<<grid, THREADS, shmem>>>(x, M1, M2, W1, W2, out);
}

// round 3
// speedup vs baseline: 3.0659x; 3.0659x over previous
#include <cuda_runtime.h>
#include <cuda_bf16.h>
#include <cstdint>

// LNLieBracketChannelMix via mma.sync bf16-split (fp32 = hi+lo bf16, 3 HMMA/product).
// out[b,g,k,n] = x[b,g,k,n] + cross(M2@d2, M1@d1)[k],  d_i = W_i @ x[b] over f.
// (tcgen05 is unavailable: harness ptxas target is sm_103, not sm_103a.)

#define B_    8
#define F_    256
#define NDIM  4096
#define COLS  12288         // 3*NDIM
#define GT    64            // g per CTA
#define NT    32            // n per CTA
#define CT    96            // 3 k-slices * NT
#define KC    32            // f chunk
#define NCH   8
#define THREADS 128

#define A_STRIDE 80         // bytes per A row (32 bf16 = 64B + 16B pad)
#define B_STRIDE 208        // bytes per B row (96 bf16 = 192B + 16B pad)
#define A_PART   (GT * A_STRIDE)        // 5120
#define B_PART   (KC * B_STRIDE)        // 6656
#define BH_OFF   (4 * A_PART)           // 20480
#define BL_OFF   (BH_OFF + B_PART)      // 27136
#define STAGE    (BH_OFF + 2 * B_PART)  // 33792
#define SMEM_TOTAL (2 * STAGE)          // 67584 (epilogue needs 49152, reused)

static __device__ __forceinline__ uint32_t s2u(const void* p) {
    uint32_t a;
    asm("{ .reg .u64 t; cvta.to.shared.u64 t, %1; cvt.u32.u64 %0, t; }" : "=r"(a) : "l"(p));
    return a;
}
static __device__ __forceinline__ void lm4(uint32_t* r, uint32_t a) {
    asm volatile("ldmatrix.sync.aligned.m8n8.x4.shared.b16 {%0,%1,%2,%3}, [%4];"
        : "=r"(r[0]), "=r"(r[1]), "=r"(r[2]), "=r"(r[3]) : "r"(a));
}
static __device__ __forceinline__ void lm4t(uint32_t* r, uint32_t a) {
    asm volatile("ldmatrix.sync.aligned.m8n8.x4.trans.shared.b16 {%0,%1,%2,%3}, [%4];"
        : "=r"(r[0]), "=r"(r[1]), "=r"(r[2]), "=r"(r[3]) : "r"(a));
}
static __device__ __forceinline__ void mma(float* d, const uint32_t* a, uint32_t b0, uint32_t b1) {
    asm volatile(
        "mma.sync.aligned.m16n8k16.row.col.f32.bf16.bf16.f32 "
        "{%0,%1,%2,%3}, {%4,%5,%6,%7}, {%8,%9}, {%0,%1,%2,%3};"
        : "+f"(d[0]), "+f"(d[1]), "+f"(d[2]), "+f"(d[3])
        : "r"(a[0]), "r"(a[1]), "r"(a[2]), "r"(a[3]), "r"(b0), "r"(b1));
}
static __device__ __forceinline__ uint32_t pk2(__nv_bfloat16 a, __nv_bfloat16 b) {
    __nv_bfloat162 t = __halves2bfloat162(a, b);
    return *reinterpret_cast<uint32_t*>(&t);
}
// split float4 into hi/lo bf16x4
static __device__ __forceinline__ void split4(float4 w, uint2& hv, uint2& lv) {
    __nv_bfloat16 hx = __float2bfloat16(w.x), hy = __float2bfloat16(w.y);
    __nv_bfloat16 hz = __float2bfloat16(w.z), hw = __float2bfloat16(w.w);
    hv.x = pk2(hx, hy); hv.y = pk2(hz, hw);
    lv.x = pk2(__float2bfloat16(w.x - __bfloat162float(hx)),
               __float2bfloat16(w.y - __bfloat162float(hy)));
    lv.y = pk2(__float2bfloat16(w.z - __bfloat162float(hz)),
               __float2bfloat16(w.w - __bfloat162float(hw)));
}

__global__ __launch_bounds__(THREADS, 2)
void lnlb_mma_kernel(const float* __restrict__ x,
                     const float* __restrict__ M1,
                     const float* __restrict__ M2,
                     const float* __restrict__ W1,
                     const float* __restrict__ W2,
                     float* __restrict__ out)
{
    extern __shared__ char smem[];
    const uint32_t sb = s2u(smem);

    const int tid = threadIdx.x;
    const int warp = tid >> 5, lane = tid & 31;
    const int n0 = blockIdx.x * NT;
    const int g0 = blockIdx.y * GT;
    const int b  = blockIdx.z;
    const float* xb = x + (size_t)b * F_ * COLS;

    const int wg = (warp >> 1) * 32;     // warp g offset (0/32)
    const int wc = (warp & 1) * 48;      // warp col offset (0/48)

    float a1[2][6][4], a2[2][6][4];
    #pragma unroll
    for (int m = 0; m < 2; m++)
        #pragma unroll
        for (int t = 0; t < 6; t++)
            #pragma unroll
            for (int j = 0; j < 4; j++) { a1[m][t][j] = 0.f; a2[m][t][j] = 0.f; }

    // ldmatrix lane offsets
    const int lrow = lane & 15;
    const uint32_t lhA = (lane & 16) ? 16u : 0u;  // +8 bf16 cols (bytes)
    const uint32_t lhB = (lane & 16) ? 8u  : 0u;  // +8 cols
    uint32_t aoff[2], boff[3];
    #pragma unroll
    for (int m = 0; m < 2; m++) aoff[m] = (uint32_t)((wg + 16 * m + lrow) * A_STRIDE) + lhA;
    #pragma unroll
    for (int t = 0; t < 3; t++) boff[t] = (uint32_t)(lrow * B_STRIDE + (wc + t * 16 + lhB) * 2);

    // ---- staging helper (chunk c into buffer buf) ----
    auto stage = [&](int c, char* buf) {
        const int f0 = c * KC;
        // A: W1,W2 chunk [64 g x 32 f] -> 4 bf16 tiles (w1h,w1l,w2h,w2l)
        #pragma unroll
        for (int i = tid; i < 1024; i += THREADS) {
            int w = i >> 9, r = i & 511, g = r >> 3, fq = r & 7;
            const float* W = w ? W2 : W1;
            float4 v = *(const float4*)(W + (g0 + g) * F_ + f0 + fq * 4);
            uint2 hv, lv; split4(v, hv, lv);
            char* dst = buf + w * 2 * A_PART + g * A_STRIDE + fq * 8;
            *(uint2*)dst = hv;
            *(uint2*)(dst + A_PART) = lv;
        }
        // B: x chunk [32 f x 96 cols] -> hi/lo
        #pragma unroll
        for (int i = tid; i < 768; i += THREADS) {
            int f = i / 24, cq = i % 24;
            const float* src = xb + (size_t)(f0 + f) * COLS + (cq >> 3) * NDIM + n0 + (cq & 7) * 4;
            float4 v = *(const float4*)src;
            uint2 hv, lv; split4(v, hv, lv);
            uint32_t off = (uint32_t)(f * B_STRIDE + cq * 8);
            *(uint2*)(buf + BH_OFF + off) = hv;
            *(uint2*)(buf + BL_OFF + off) = lv;
        }
    };

    stage(0, smem);
    __syncthreads();

    for (int c = 0; c < NCH; ++c) {
        if (c + 1 < NCH) stage(c + 1, smem + ((c + 1) & 1) * STAGE);

        const uint32_t bu = sb + (uint32_t)((c & 1) * STAGE);
        #pragma unroll
        for (int ks2 = 0; ks2 < 2; ++ks2) {
            const uint32_t ksA = ks2 * 32;              // 16 bf16 = 32 B
            const uint32_t ksB = ks2 * 16 * B_STRIDE;   // 16 rows

            uint32_t A1h[2][4], A1l[2][4], A2h[2][4], A2l[2][4];
            #pragma unroll
            for (int m = 0; m < 2; m++) {
                lm4(A1h[m], bu + 0 * A_PART + aoff[m] + ksA);
                lm4(A1l[m], bu + 1 * A_PART + aoff[m] + ksA);
                lm4(A2h[m], bu + 2 * A_PART + aoff[m] + ksA);
                lm4(A2l[m], bu + 3 * A_PART + aoff[m] + ksA);
            }
            uint32_t BH[3][4], BL[3][4];
            #pragma unroll
            for (int t = 0; t < 3; t++) {
                lm4t(BH[t], bu + BH_OFF + boff[t] + ksB);
                lm4t(BL[t], bu + BL_OFF + boff[t] + ksB);
            }
            #pragma unroll
            for (int m = 0; m < 2; m++)
                #pragma unroll
                for (int t = 0; t < 3; t++) {
                    mma(a1[m][2*t],   A1h[m], BH[t][0], BH[t][1]);
                    mma(a1[m][2*t],   A1h[m], BL[t][0], BL[t][1]);
                    mma(a1[m][2*t],   A1l[m], BH[t][0], BH[t][1]);
                    mma(a1[m][2*t+1], A1h[m], BH[t][2], BH[t][3]);
                    mma(a1[m][2*t+1], A1h[m], BL[t][2], BL[t][3]);
                    mma(a1[m][2*t+1], A1l[m], BH[t][2], BH[t][3]);
                    mma(a2[m][2*t],   A2h[m], BH[t][0], BH[t][1]);
                    mma(a2[m][2*t],   A2h[m], BL[t][0], BL[t][1]);
                    mma(a2[m][2*t],   A2l[m], BH[t][0], BH[t][1]);
                    mma(a2[m][2*t+1], A2h[m], BH[t][2], BH[t][3]);
                    mma(a2[m][2*t+1], A2h[m], BL[t][2], BL[t][3]);
                    mma(a2[m][2*t+1], A2l[m], BH[t][2], BH[t][3]);
                }
        }
        __syncthreads();
    }

    // ---- dump accumulators to smem (reuse stage buffers) ----
    float* D1s = (float*)smem;
    float* D2s = D1s + GT * CT;
    {
        const int dr = wg + (lane >> 2);
        const int dc = wc + (lane & 3) * 2;
        #pragma unroll
        for (int m = 0; m < 2; m++)
            #pragma unroll
            for (int t = 0; t < 6; t++) {
                int r0 = dr + 16 * m, cc = dc + t * 8;
                D1s[r0 * CT + cc]       = a1[m][t][0];
                D1s[r0 * CT + cc + 1]   = a1[m][t][1];
                D1s[(r0+8) * CT + cc]   = a1[m][t][2];
                D1s[(r0+8) * CT + cc+1] = a1[m][t][3];
                D2s[r0 * CT + cc]       = a2[m][t][0];
                D2s[r0 * CT + cc + 1]   = a2[m][t][1];
                D2s[(r0+8) * CT + cc]   = a2[m][t][2];
                D2s[(r0+8) * CT + cc+1] = a2[m][t][3];
            }
    }
    __syncthreads();

    // ---- epilogue: rotate by M1/M2, cross, add x ----
    float m1[9], m2[9];
    #pragma unroll
    for (int i = 0; i < 9; i++) { m1[i] = M1[i]; m2[i] = M2[i]; }

    #pragma unroll
    for (int p = tid; p < GT * NT; p += THREADS) {
        int g = p >> 5, nn = p & 31;
        float e10 = D1s[g * CT + 0 * NT + nn];
        float e11 = D1s[g * CT + 1 * NT + nn];
        float e12 = D1s[g * CT + 2 * NT + nn];
        float e20 = D2s[g * CT + 0 * NT + nn];
        float e21 = D2s[g * CT + 1 * NT + nn];
        float e22 = D2s[g * CT + 2 * NT + nn];
        float q0 = fmaf(m1[0], e10, fmaf(m1[1], e11, m1[2] * e12));
        float q1 = fmaf(m1[3], e10, fmaf(m1[4], e11, m1[5] * e12));
        float q2 = fmaf(m1[6], e10, fmaf(m1[7], e11, m1[8] * e12));
        float r0 = fmaf(m2[0], e20, fmaf(m2[1], e21, m2[2] * e22));
        float r1 = fmaf(m2[3], e20, fmaf(m2[4], e21, m2[5] * e22));
        float r2 = fmaf(m2[6], e20, fmaf(m2[7], e21, m2[8] * e22));
        float v0 = r1 * q2 - r2 * q1;   // cross(M2 d2, M1 d1)
        float v1 = r2 * q0 - r0 * q2;
        float v2 = r0 * q1 - r1 * q0;

        size_t base = ((size_t)(b * F_ + g0 + g) * 3) * NDIM + n0 + nn;
        out[base]            = x[base]            + v0;
        out[base + NDIM]     = x[base + NDIM]     + v1;
        out[base + 2 * NDIM] = x[base + 2 * NDIM] + v2;
    }
}

extern "C" void kernel_launch(void* const* d_in, const int* in_sizes, int n_in,
                              void* d_out, int out_size)
{
    const float* x  = (const float*)d_in[0];
    const float* M1 = (const float*)d_in[1];
    const float* M2 = (const float*)d_in[2];
    const float* W1 = (const float*)d_in[3];
    const float* W2 = (const float*)d_in[4];
    float* out = (float*)d_out;

    cudaFuncSetAttribute(lnlb_mma_kernel, cudaFuncAttributeMaxDynamicSharedMemorySize, SMEM_TOTAL);
    dim3 grid(NDIM / NT, F_ / GT, B_);   // (128, 4, 8)
    lnlb_mma_kernel<<<grid, THREADS, SMEM_TOTAL>>>(x, M1, M2, W1, W2, out);
}